// round 16
// baseline (speedup 1.0000x reference)
#include <cuda_runtime.h>
#include <cstdint>
#include <cstddef>

typedef unsigned long long ull;
#define DI __device__ __forceinline__

DI ull pack2(float x, float y){ ull r; asm("mov.b64 %0,{%1,%2};":"=l"(r):"f"(x),"f"(y)); return r; }
DI float2 unp2(ull v){ float2 r; asm("mov.b64 {%0,%1},%2;":"=f"(r.x),"=f"(r.y):"l"(v)); return r; }
DI ull fma2(ull a, ull b, ull c){ ull d; asm("fma.rn.f32x2 %0,%1,%2,%3;":"=l"(d):"l"(a),"l"(b),"l"(c)); return d; }
DI ull mul2(ull a, ull b){ ull d; asm("mul.rn.f32x2 %0,%1,%2;":"=l"(d):"l"(a),"l"(b)); return d; }

DI void cpa16(void* dst_smem, const void* src_gmem){
    uint32_t s = (uint32_t)__cvta_generic_to_shared(dst_smem);
    asm volatile("cp.async.cg.shared.global [%0], [%1], 16;\n" :: "r"(s), "l"(src_gmem) : "memory");
}
DI void cpa_commit(){ asm volatile("cp.async.commit_group;\n" ::: "memory"); }
template<int N> DI void cpa_wait(){ asm volatile("cp.async.wait_group %0;\n" :: "n"(N) : "memory"); }

constexpr int B_ = 2, S_ = 512, H_ = 8, D_ = 32, DM_ = 256;
constexpr int M_ = B_ * S_;

__device__ float g_q [M_ * DM_];
__device__ float g_k [M_ * DM_];
__device__ float g_v [M_ * DM_];

// ---------------------------------------------------------------------------
// Kernel 1: QKV projections (unchanged from best). 32x64 tiles, depth-3,
// 4x4 reg tile ping-pong. grid (4, 32, 3) = 384 blocks, 128 threads.
// ---------------------------------------------------------------------------
__global__ void __launch_bounds__(128) qkv_k(const float* __restrict__ x,
                                             const float* __restrict__ wq,
                                             const float* __restrict__ wk,
                                             const float* __restrict__ wv)
{
    __shared__ float As3[3][32 * 36];
    __shared__ float Bs3[3][32 * 64];
    const int bz = blockIdx.z;
    const float* w = (bz == 0) ? wq : ((bz == 1) ? wk : wv);
    float* out = (bz == 0) ? g_q : ((bz == 1) ? g_k : g_v);
    const int m0 = blockIdx.y * 32, n0 = blockIdx.x * 64;
    const int tid = threadIdx.x, tx = tid & 15, ty = tid >> 4;

    auto stage = [&](int kt){
        int buf = kt % 3, k0 = kt * 32;
        float* As = As3[buf];
        float* Bs = Bs3[buf];
        #pragma unroll
        for (int r = 0; r < 2; r++) {
            int f = r * 128 + tid; int row = f >> 3, kq = f & 7;
            cpa16(As + row * 36 + kq * 4, x + (size_t)(m0 + row) * DM_ + k0 + kq * 4);
        }
        #pragma unroll
        for (int r = 0; r < 4; r++) {
            int f = r * 128 + tid; int kk = f >> 4, nq = f & 15;
            cpa16(Bs + kk * 64 + nq * 4, w + (size_t)(k0 + kk) * DM_ + n0 + nq * 4);
        }
    };

    ull acc[4][2];
    #pragma unroll
    for (int r = 0; r < 4; r++) { acc[r][0] = 0ull; acc[r][1] = 0ull; }

    stage(0); cpa_commit();
    stage(1); cpa_commit();
    stage(2); cpa_commit();

    for (int kt = 0; kt < 8; kt++) {
        if (kt + 2 < 8) cpa_wait<2>(); else if (kt + 1 < 8) cpa_wait<1>(); else cpa_wait<0>();
        __syncthreads();
        const float* As = As3[kt % 3];
        const float* Bs = Bs3[kt % 3];

        float4     aR[2][4];
        ulonglong2 bR[2][4];
        #pragma unroll
        for (int r = 0; r < 4; r++)
            aR[0][r] = *(const float4*)(As + (ty * 4 + r) * 36);
        #pragma unroll
        for (int kk = 0; kk < 4; kk++)
            bR[0][kk] = *(const ulonglong2*)(Bs + kk * 64 + tx * 4);

        #pragma unroll
        for (int k4 = 0; k4 < 8; k4++) {
            const int cur = k4 & 1, nxt = cur ^ 1;
            if (k4 < 7) {
                #pragma unroll
                for (int r = 0; r < 4; r++)
                    aR[nxt][r] = *(const float4*)(As + (ty * 4 + r) * 36 + (k4 + 1) * 4);
                #pragma unroll
                for (int kk = 0; kk < 4; kk++)
                    bR[nxt][kk] = *(const ulonglong2*)(Bs + ((k4 + 1) * 4 + kk) * 64 + tx * 4);
            }
            #pragma unroll
            for (int kk = 0; kk < 4; kk++) {
                #pragma unroll
                for (int r = 0; r < 4; r++) {
                    float a = ((const float*)&aR[cur][r])[kk];
                    ull ap = pack2(a, a);
                    acc[r][0] = fma2(ap, bR[cur][kk].x, acc[r][0]);
                    acc[r][1] = fma2(ap, bR[cur][kk].y, acc[r][1]);
                }
            }
        }
        __syncthreads();
        if (kt + 3 < 8) { stage(kt + 3); cpa_commit(); }
    }
    #pragma unroll
    for (int r = 0; r < 4; r++) {
        float2 lo = unp2(acc[r][0]), hi = unp2(acc[r][1]);
        float4 o; o.x = lo.x; o.y = lo.y; o.z = hi.x; o.w = hi.y;
        *(float4*)(out + (size_t)(m0 + ty * 4 + r) * DM_ + n0 + tx * 4) = o;
    }
}

// ---------------------------------------------------------------------------
// Kernel 2 (FUSED): attention + epilogue GEMM + layernorm. 512 thr, grid (64,2).
// Attention part identical to best (JT=32, depth-2, rpe pad 1156).
// Fused tail: AV out -> ao_s (smem, reuses rpe region); fc_w staged 32-k
// chunks through the q/v buffers; + fc_b + residual -> ctx; warp/row LN -> out.
// ---------------------------------------------------------------------------
constexpr int JT  = 32;
constexpr int QSB = JT * 292;                    // 9344 floats per q/v buf
constexpr int RPB = 8 * 1156;                    // 9248 floats per rpe buf
constexpr int OFF_QS = 0;
constexpr int OFF_RP = 2 * QSB;                  // 18688
constexpr int OFF_SC = OFF_RP + 2 * RPB;         // 37184 ; sc [64][260]
constexpr int SCS = 260;
constexpr int A_SMEM_FLOATS = OFF_SC + 64 * SCS; // 53824
constexpr int A_SMEM_BYTES  = A_SMEM_FLOATS * 4; // 215,296 B -> 1 CTA/SM
// epilogue aliases (regions dead by then): ao_s/ctx over rpe bufs, fw over qv
constexpr int OFF_AO  = OFF_RP;                  // 8 x 260
constexpr int OFF_CTX = OFF_RP + 8 * 260;        // 8 x 260

__global__ void __launch_bounds__(512, 1) attn_k(const float* __restrict__ rpe,
                                                 const int* __restrict__ snp,
                                                 const float* __restrict__ hs,
                                                 const float* __restrict__ fw,
                                                 const float* __restrict__ fb,
                                                 const float* __restrict__ lw,
                                                 const float* __restrict__ lb,
                                                 float* __restrict__ out)
{
    extern __shared__ float sm[];
    float* sc = sm + OFF_SC;
    const int tid = threadIdx.x;
    const int w = tid >> 5, lane = tid & 31;
    const int il = lane >> 3, h = lane & 7;
    const int b = blockIdx.y, i0 = blockIdx.x * 8;
    int sn = *snp; if (sn > 256) sn = 256; if (sn < 0) sn = 0;
    const int nt = (sn + JT - 1) / JT;
    const float scale = 0.17677669529663687f;

    ull kp0[16], kp1[16];
    {
        const float* kg0 = g_k + (size_t)(b * S_ + i0 + il) * DM_ + h * 32;
        const float* kg1 = kg0 + (size_t)4 * DM_;
        #pragma unroll
        for (int t = 0; t < 8; t++) {
            float4 a = *(const float4*)(kg0 + t * 4);
            kp0[2 * t] = pack2(a.x, a.y); kp0[2 * t + 1] = pack2(a.z, a.w);
            float4 c = *(const float4*)(kg1 + t * 4);
            kp1[2 * t] = pack2(c.x, c.y); kp1[2 * t + 1] = pack2(c.z, c.w);
        }
    }

    auto stage_qv = [&](const float* src_base, int t){
        int buf = t & 1, j0 = t * JT;
        #pragma unroll
        for (int r = 0; r < 4; r++) {
            int f = r * 512 + tid; int row = f >> 6, cq = f & 63;
            cpa16(sm + OFF_QS + buf * QSB + row * 292 + (cq >> 3) * 36 + (cq & 7) * 4,
                  src_base + (size_t)(b * S_ + j0 + row) * DM_ + cq * 4);
        }
    };
    auto stage_rpe = [&](int t){
        int buf = t & 1, j0 = t * JT;
        #pragma unroll
        for (int r = 0; r < 4; r++) {
            int f = r * 512 + tid; int ii = f >> 8, j = (f >> 3) & 31, dq = f & 7;
            cpa16(sm + OFF_RP + buf * RPB + ii * 1156 + j * 36 + dq * 4,
                  rpe + ((size_t)(b * S_ + i0 + ii) * S_ + j0 + j) * D_ + dq * 4);
        }
    };

    if (nt > 0) { stage_qv(g_q, 0); stage_rpe(0); cpa_commit(); }
    if (nt > 1) { stage_qv(g_q, 1); stage_rpe(1); cpa_commit(); }

    // ----- score phase -----
    for (int t = 0; t < nt; t++) {
        if (t + 1 < nt) cpa_wait<1>(); else cpa_wait<0>();
        __syncthreads();
        const int buf = t & 1;
        #pragma unroll
        for (int jj = 0; jj < 2; jj++) {
            const int j = w + jj * 16, jg = t * JT + j;
            const float* qrow = sm + OFF_QS + buf * QSB + j * 292 + h * 36;
            const float* rp0  = sm + OFF_RP + buf * RPB + il * 1156 + j * 36;
            const float* rp1  = rp0 + 4 * 1156;
            ull a0 = 0ull, a1 = 0ull;
            #pragma unroll
            for (int d4 = 0; d4 < 8; d4++) {
                ulonglong2 q2 = *(const ulonglong2*)(qrow + d4 * 4);
                ulonglong2 r0 = *(const ulonglong2*)(rp0 + d4 * 4);
                a0 = fma2(mul2(q2.x, kp0[2 * d4]),     r0.x, a0);
                a0 = fma2(mul2(q2.y, kp0[2 * d4 + 1]), r0.y, a0);
                ulonglong2 r1 = *(const ulonglong2*)(rp1 + d4 * 4);
                a1 = fma2(mul2(q2.x, kp1[2 * d4]),     r1.x, a1);
                a1 = fma2(mul2(q2.y, kp1[2 * d4 + 1]), r1.y, a1);
            }
            if (jg < sn) {
                float2 t0 = unp2(a0), t1 = unp2(a1);
                sc[(il * 8 + h) * SCS + jg]       = (t0.x + t0.y) * scale;
                sc[((il + 4) * 8 + h) * SCS + jg] = (t1.x + t1.y) * scale;
            }
        }
        __syncthreads();
        if (t + 2 < nt) { stage_qv(g_q, t + 2); stage_rpe(t + 2); cpa_commit(); }
    }

    if (nt > 0) { stage_qv(g_v, 0); cpa_commit(); }
    if (nt > 1) { stage_qv(g_v, 1); cpa_commit(); }

    // diagonal scores
    if (tid < 64) {
        int di = tid >> 3, dh = tid & 7;
        int ig = i0 + di;
        if (ig >= sn) {
            const float* qg = g_q + (size_t)(b * S_ + ig) * DM_ + dh * 32;
            const float* kg = g_k + (size_t)(b * S_ + ig) * DM_ + dh * 32;
            const float* rg = rpe + ((size_t)(b * S_ + ig) * S_ + ig) * D_;
            ull acc = 0ull;
            #pragma unroll
            for (int t = 0; t < 8; t++) {
                float4 qf = *(const float4*)(qg + t * 4);
                float4 kf = *(const float4*)(kg + t * 4);
                float4 rf = *(const float4*)(rg + t * 4);
                acc = fma2(mul2(pack2(qf.x, qf.y), pack2(kf.x, kf.y)), pack2(rf.x, rf.y), acc);
                acc = fma2(mul2(pack2(qf.z, qf.w), pack2(kf.z, kf.w)), pack2(rf.z, rf.w), acc);
            }
            float2 tt = unp2(acc);
            sc[(di * 8 + dh) * SCS + 256] = (tt.x + tt.y) * scale;
        }
    }
    __syncthreads();

    // ----- softmax -----
    {
        const int jmax = nt * JT;
        for (int rr = 0; rr < 4; rr++) {
            int row = w * 4 + rr;
            bool hd = (i0 + (row >> 3)) >= sn;
            float* srow = &sc[row * SCS];
            float mx = -1e30f;
            for (int jj = lane; jj < sn; jj += 32) mx = fmaxf(mx, srow[jj]);
            if (hd && lane == 0) mx = fmaxf(mx, srow[256]);
            #pragma unroll
            for (int o = 16; o > 0; o >>= 1) mx = fmaxf(mx, __shfl_xor_sync(0xffffffffu, mx, o));
            float sum = 0.f;
            for (int jj = lane; jj < jmax; jj += 32) {
                float p = (jj < sn) ? __expf(srow[jj] - mx) : 0.f;
                srow[jj] = p; sum += p;
            }
            if (hd && lane == 0) { float p = __expf(srow[256] - mx); srow[256] = p; sum += p; }
            #pragma unroll
            for (int o = 16; o > 0; o >>= 1) sum += __shfl_xor_sync(0xffffffffu, sum, o);
            float rn = 1.f / sum;
            for (int jj = lane; jj < jmax; jj += 32) srow[jj] *= rn;
            if (hd && lane == 0) srow[256] *= rn;
        }
    }

    // ----- AV: thread owns (ai, ah, dc); result = ao row ai, cols ah*32+dc*4 -
    const int ai = tid >> 6, ah = (tid >> 3) & 7, dc = tid & 7;
    ull a0 = 0ull, a1 = 0ull;
    for (int t = 0; t < nt; t++) {
        if (t + 1 < nt) cpa_wait<1>(); else cpa_wait<0>();
        __syncthreads();
        const float* vb = sm + OFF_QS + (t & 1) * QSB;
        #pragma unroll
        for (int g = 0; g < 8; g++) {
            float4 p4 = *(const float4*)&sc[(ai * 8 + ah) * SCS + t * JT + g * 4];
            const float pv[4] = {p4.x, p4.y, p4.z, p4.w};
            #pragma unroll
            for (int jj = 0; jj < 4; jj++) {
                ulonglong2 v2 = *(const ulonglong2*)(vb + (g * 4 + jj) * 292 + ah * 36 + dc * 4);
                ull pk = pack2(pv[jj], pv[jj]);
                a0 = fma2(pk, v2.x, a0);
                a1 = fma2(pk, v2.y, a1);
            }
        }
        __syncthreads();
        if (t + 2 < nt) { stage_qv(g_v, t + 2); cpa_commit(); }
    }
    {
        int ig = i0 + ai;
        if (ig >= sn) {
            float p = sc[(ai * 8 + ah) * SCS + 256];
            float4 vd = *(const float4*)(g_v + (size_t)(b * S_ + ig) * DM_ + ah * 32 + dc * 4);
            ull pk = pack2(p, p);
            a0 = fma2(pk, pack2(vd.x, vd.y), a0);
            a1 = fma2(pk, pack2(vd.z, vd.w), a1);
        }
        float2 lo = unp2(a0), hi = unp2(a1);
        float4 o; o.x = lo.x; o.y = lo.y; o.z = hi.x; o.w = hi.y;
        *(float4*)(sm + OFF_AO + ai * 260 + ah * 32 + dc * 4) = o;   // -> smem
    }
    __syncthreads();

    // ----- fused epilogue GEMM: ctx = ao_s @ fc_w + fc_b + hs -----
    // thread = (rh = tid>>6, cp = tid&63) -> 4 cols (4*cp). fc_w staged in
    // 32-k chunks (32x260 floats) double-buffered in the dead q/v buffers.
    auto stage_w = [&](int kt){
        int buf = kt & 1, k0 = kt * 32;
        #pragma unroll
        for (int r = 0; r < 4; r++) {
            int f = r * 512 + tid; int kr = f >> 6, cq = f & 63;
            cpa16(sm + OFF_QS + buf * QSB + kr * 260 + cq * 4,
                  fw + (size_t)(k0 + kr) * DM_ + cq * 4);
        }
    };
    stage_w(0); cpa_commit();
    stage_w(1); cpa_commit();

    const int rh = tid >> 6, cp = tid & 63;
    const float* ar = sm + OFF_AO + rh * 260;
    ull e0 = 0ull, e1 = 0ull;
    for (int kt = 0; kt < 8; kt++) {
        if (kt + 1 < 8) cpa_wait<1>(); else cpa_wait<0>();
        __syncthreads();
        const float* wb = sm + OFF_QS + (kt & 1) * QSB;
        const float* ak = ar + kt * 32;
        #pragma unroll 8
        for (int kk = 0; kk < 32; kk++) {
            float a = ak[kk];
            ulonglong2 w2 = *(const ulonglong2*)(wb + kk * 260 + 4 * cp);
            ull ap = pack2(a, a);
            e0 = fma2(ap, w2.x, e0);
            e1 = fma2(ap, w2.y, e1);
        }
        __syncthreads();
        if (kt + 2 < 8) { stage_w(kt + 2); cpa_commit(); }
    }
    {
        const int grow = b * S_ + i0 + rh;
        float4 fb4 = *(const float4*)(fb + 4 * cp);
        float4 h4  = *(const float4*)(hs + (size_t)grow * DM_ + 4 * cp);
        float2 lo = unp2(e0), hi = unp2(e1);
        float4 o;
        o.x = lo.x + fb4.x + h4.x; o.y = lo.y + fb4.y + h4.y;
        o.z = hi.x + fb4.z + h4.z; o.w = hi.y + fb4.w + h4.w;
        *(float4*)(sm + OFF_CTX + rh * 260 + 4 * cp) = o;
    }
    __syncthreads();

    // ----- layernorm: warps 0..7, one row each -----
    if (w < 8) {
        const float* xr = sm + OFF_CTX + w * 260 + lane * 8;
        float4 x0 = *(const float4*)xr;
        float4 x1 = *(const float4*)(xr + 4);
        float s = x0.x + x0.y + x0.z + x0.w + x1.x + x1.y + x1.z + x1.w;
        #pragma unroll
        for (int o = 16; o > 0; o >>= 1) s += __shfl_xor_sync(0xffffffffu, s, o);
        float mu = s * (1.f / 256.f);
        float xs[8] = {x0.x, x0.y, x0.z, x0.w, x1.x, x1.y, x1.z, x1.w};
        float v = 0.f;
        #pragma unroll
        for (int k = 0; k < 8; k++) { float d = xs[k] - mu; v += d * d; }
        #pragma unroll
        for (int o = 16; o > 0; o >>= 1) v += __shfl_xor_sync(0xffffffffu, v, o);
        float rs = rsqrtf(v * (1.f / 256.f) + 1e-6f);
        const int c = lane * 8;
        float4 lw0 = *(const float4*)(lw + c), lw1 = *(const float4*)(lw + c + 4);
        float4 lb0 = *(const float4*)(lb + c), lb1 = *(const float4*)(lb + c + 4);
        float4 y0, y1;
        y0.x = (xs[0]-mu)*rs*lw0.x + lb0.x; y0.y = (xs[1]-mu)*rs*lw0.y + lb0.y;
        y0.z = (xs[2]-mu)*rs*lw0.z + lb0.z; y0.w = (xs[3]-mu)*rs*lw0.w + lb0.w;
        y1.x = (xs[4]-mu)*rs*lw1.x + lb1.x; y1.y = (xs[5]-mu)*rs*lw1.y + lb1.y;
        y1.z = (xs[6]-mu)*rs*lw1.z + lb1.z; y1.w = (xs[7]-mu)*rs*lw1.w + lb1.w;
        size_t ro = (size_t)(b * S_ + i0 + w) * DM_ + c;
        *(float4*)(out + ro)     = y0;
        *(float4*)(out + ro + 4) = y1;
    }
}

// ---------------------------------------------------------------------------
extern "C" void kernel_launch(void* const* d_in, const int* in_sizes, int n_in,
                              void* d_out, int out_size)
{
    const float* hs  = (const float*)d_in[0];
    const float* rpe = (const float*)d_in[1];
    const float* wq  = (const float*)d_in[2];
    const float* wk  = (const float*)d_in[3];
    const float* wv  = (const float*)d_in[4];
    const float* fw  = (const float*)d_in[5];
    const float* fb  = (const float*)d_in[6];
    const float* lw  = (const float*)d_in[7];
    const float* lb  = (const float*)d_in[8];
    const int*   sn  = (const int*)  d_in[9];
    float* out = (float*)d_out;

    cudaFuncSetAttribute(attn_k, cudaFuncAttributeMaxDynamicSharedMemorySize, A_SMEM_BYTES);

    qkv_k<<<dim3(4, 32, 3), 128>>>(hs, wq, wk, wv);
    attn_k<<<dim3(64, 2), 512, A_SMEM_BYTES>>>(rpe, sn, hs, fw, fb, lw, lb, out);
}